// round 13
// baseline (speedup 1.0000x reference)
#include <cuda_runtime.h>
#include <cstdint>

#define BB 64
#define HH 16
#define DD 128
#define S_TOT 4096
#define EE 2048
#define NSPLIT 4
#define CHUNK 1024
#define SUB 64
#define KSPLIT 8
#define KCH 256

typedef unsigned long long ull;

__device__ float g_q[BB][EE];
__device__ float g_kn[BB][DD];
__device__ float g_vn[BB][DD];
__device__ float g_po[BB][NSPLIT][HH][DD];
__device__ float g_pm[BB][NSPLIT][HH];
__device__ float g_pl[BB][NSPLIT][HH];
__device__ float g_attn[BB][EE];
__device__ float g_part[KSPLIT][BB][2304];
__device__ float g_part2[KSPLIT][BB][EE];

__device__ __forceinline__ ull ffma2u(ull a, ull b, ull c) {
    ull d;
    asm("fma.rn.f32x2 %0, %1, %2, %3;" : "=l"(d) : "l"(a), "l"(b), "l"(c));
    return d;
}
__device__ __forceinline__ ull f2u(float x, float y) {
    ull u;
    asm("mov.b64 %0, {%1,%2};" : "=l"(u) : "f"(x), "f"(y));
    return u;
}
__device__ __forceinline__ float2 u2f(ull u) {
    float2 f;
    asm("mov.b64 {%0,%1}, %2;" : "=f"(f.x), "=f"(f.y) : "l"(u));
    return f;
}

__global__ void noop_kernel() {}

// ===================== attention: mma.sync 3xTF32 + cp.async =====================
// smem (bytes): kv[64][132] f32 @0 (33792) | qh[16][132] @33792 | ql @42240
//               PH[64][24] @50688 | PL @56832 | lsw[8][8] @62976 ; total 63232
#define KV_OFF 0
#define QH_OFF 33792
#define QL_OFF 42240
#define PH_OFF 50688
#define PL_OFF 56832
#define LS_OFF 62976
#define SMEM_ATTN 63232

__device__ __forceinline__ uint32_t cvt_tf32(float x) {
    uint32_t r;
    asm("cvt.rna.tf32.f32 %0, %1;" : "=r"(r) : "f"(x));
    return r;
}
__device__ __forceinline__ void mma8(float* d, const uint32_t* a,
                                     const uint32_t* b) {
    asm volatile(
        "mma.sync.aligned.m16n8k8.row.col.f32.tf32.tf32.f32 "
        "{%0,%1,%2,%3},{%4,%5,%6,%7},{%8,%9},{%0,%1,%2,%3};"
        : "+f"(d[0]), "+f"(d[1]), "+f"(d[2]), "+f"(d[3])
        : "r"(a[0]), "r"(a[1]), "r"(a[2]), "r"(a[3]), "r"(b[0]), "r"(b[1]));
}
__device__ __forceinline__ void split_tf32(float x, uint32_t& hi, uint32_t& lo) {
    hi = cvt_tf32(x);
    lo = cvt_tf32(x - __uint_as_float(hi));
}
__device__ __forceinline__ void cp16(uint32_t dst, const void* src) {
    asm volatile("cp.async.cg.shared.global [%0], [%1], 16;"
                 :: "r"(dst), "l"(src));
}
__device__ __forceinline__ void cp_wait() {
    asm volatile("cp.async.commit_group;");
    asm volatile("cp.async.wait_group 0;" ::: "memory");
}

__global__ void __launch_bounds__(256, 3) attn_kernel(
    const float* __restrict__ kc, const float* __restrict__ vc,
    const int* __restrict__ pos) {
    extern __shared__ char smem[];
    float* kv = (float*)(smem + KV_OFF);
    uint32_t* qh = (uint32_t*)(smem + QH_OFF);
    uint32_t* ql = (uint32_t*)(smem + QL_OFF);
    uint32_t* PH = (uint32_t*)(smem + PH_OFF);
    uint32_t* PL = (uint32_t*)(smem + PL_OFF);
    float* lsw = (float*)(smem + LS_OFF);
    const uint32_t kvs = (uint32_t)__cvta_generic_to_shared(kv);

    const int c = blockIdx.x, b = blockIdx.y;
    const int tid = threadIdx.x, w = tid >> 5, l = tid & 31;
    const int g = l >> 2, t = l & 3;

    // stage q pre-split into hi/lo tf32 planes (once per kernel)
    for (int i = tid; i < 2048; i += 256) {
        int h = i >> 7, d = i & 127;
        uint32_t hi, lo;
        split_tf32(g_q[b][h * 128 + d], hi, lo);
        qh[h * 132 + d] = hi;
        ql[h * 132 + d] = lo;
    }
    const int p_glob = pos[b];
    const size_t base = (size_t)b * S_TOT * DD;
    const float scale = 0.08838834764831845f;  // 1/sqrt(128)

    // QK geometry: warp -> 16 slots (sg), 8 heads (hg)
    const int s0 = (w >> 1) * 16;
    const int h0 = (w & 1) * 8;
    // PV geometry: warp -> 16 dims, all 16 heads
    const int d0 = w * 16;

    float accp[2][4];
#pragma unroll
    for (int n = 0; n < 2; n++)
#pragma unroll
        for (int j = 0; j < 4; j++) accp[n][j] = 0.f;
    float lsacc[2] = {0.f, 0.f};

    // per-thread load slots: i = tid + 256*it -> s = i>>5 (0..63), dq = i&31
    const int lds = tid >> 5;   // covers s = lds, lds+8, ..., lds+56
    const int ldq = tid & 31;

    for (int sub = 0; sub < CHUNK / SUB; sub++) {
        const int sbase = c * CHUNK + sub * SUB;
        __syncthreads();  // kv + P consumed by previous subtile

        // ---- K tile via cp.async (paged fix via src select) ----
#pragma unroll
        for (int it = 0; it < 8; it++) {
            int s = lds + 8 * it;
            int gs = sbase + s;
            const float* src = (gs == p_glob) ? &g_kn[b][ldq * 4]
                                              : &kc[base + (size_t)gs * DD + ldq * 4];
            cp16(kvs + (uint32_t)(s * 132 + ldq * 4) * 4, src);
        }
        cp_wait();
        __syncthreads();

        // ---- QK: C[16 slots x 8 heads] per warp, 3xTF32 ----
        float accq[4] = {0.f, 0.f, 0.f, 0.f};
#pragma unroll
        for (int k = 0; k < 16; k++) {
            const int kb = k * 8;
            float a0 = kv[(s0 + g) * 132 + kb + t];
            float a1 = kv[(s0 + g + 8) * 132 + kb + t];
            float a2 = kv[(s0 + g) * 132 + kb + t + 4];
            float a3 = kv[(s0 + g + 8) * 132 + kb + t + 4];
            uint32_t ah[4], al[4];
            split_tf32(a0, ah[0], al[0]);
            split_tf32(a1, ah[1], al[1]);
            split_tf32(a2, ah[2], al[2]);
            split_tf32(a3, ah[3], al[3]);
            uint32_t bh[2], bl[2];
            bh[0] = qh[(h0 + g) * 132 + kb + t];
            bh[1] = qh[(h0 + g) * 132 + kb + t + 4];
            bl[0] = ql[(h0 + g) * 132 + kb + t];
            bl[1] = ql[(h0 + g) * 132 + kb + t + 4];
            mma8(accq, ah, bh);
            mma8(accq, ah, bl);
            mma8(accq, al, bh);
        }

        // ---- epilogue: deferred softmax (fixed max 0), P hi/lo tf32 ----
#pragma unroll
        for (int j = 0; j < 4; j++) {
            float p = __expf(fminf(accq[j] * scale, 70.f));
            int slot = s0 + g + ((j >= 2) ? 8 : 0);
            int h = h0 + 2 * t + (j & 1);
            lsacc[j & 1] += p;
            uint32_t phi, plo;
            split_tf32(p, phi, plo);
            PH[slot * 24 + h] = phi;
            PL[slot * 24 + h] = plo;
        }
        __syncthreads();  // P visible; QK reads of kv done

        // ---- V tile via cp.async ----
#pragma unroll
        for (int it = 0; it < 8; it++) {
            int s = lds + 8 * it;
            int gs = sbase + s;
            const float* src = (gs == p_glob) ? &g_vn[b][ldq * 4]
                                              : &vc[base + (size_t)gs * DD + ldq * 4];
            cp16(kvs + (uint32_t)(s * 132 + ldq * 4) * 4, src);
        }
        cp_wait();
        __syncthreads();

        // ---- PV: C[16 dims x 16 heads] += V^T . P, 3xTF32, 8 k-steps ----
#pragma unroll
        for (int k = 0; k < 8; k++) {
            const int kb = k * 8;
            float a0 = kv[(kb + t) * 132 + d0 + g];
            float a1 = kv[(kb + t) * 132 + d0 + g + 8];
            float a2 = kv[(kb + t + 4) * 132 + d0 + g];
            float a3 = kv[(kb + t + 4) * 132 + d0 + g + 8];
            uint32_t ah[4], al[4];
            split_tf32(a0, ah[0], al[0]);
            split_tf32(a1, ah[1], al[1]);
            split_tf32(a2, ah[2], al[2]);
            split_tf32(a3, ah[3], al[3]);
#pragma unroll
            for (int n = 0; n < 2; n++) {
                uint32_t bh[2], bl[2];
                bh[0] = PH[(kb + t) * 24 + n * 8 + g];
                bh[1] = PH[(kb + t + 4) * 24 + n * 8 + g];
                bl[0] = PL[(kb + t) * 24 + n * 8 + g];
                bl[1] = PL[(kb + t + 4) * 24 + n * 8 + g];
                mma8(accp[n], ah, bh);
                mma8(accp[n], ah, bl);
                mma8(accp[n], al, bh);
            }
        }
    }

    // ---- write PV outputs ----
#pragma unroll
    for (int n = 0; n < 2; n++) {
#pragma unroll
        for (int j = 0; j < 4; j++) {
            int d = d0 + g + ((j >= 2) ? 8 : 0);
            int h = n * 8 + 2 * t + (j & 1);
            g_po[b][c][h][d] = accp[n][j];
        }
    }
    // ---- denominators: sum over g lanes, then over the 4 slot-group warps ----
#pragma unroll
    for (int jj = 0; jj < 2; jj++) {
        float v = lsacc[jj];
        v += __shfl_xor_sync(0xffffffffu, v, 4);
        v += __shfl_xor_sync(0xffffffffu, v, 8);
        v += __shfl_xor_sync(0xffffffffu, v, 16);
        if (g == 0) lsw[w * 8 + 2 * t + jj] = v;
    }
    __syncthreads();
    if (tid < 16) {
        int hg = tid >> 3, idx = tid & 7;
        float s = lsw[hg * 8 + idx] + lsw[(hg + 2) * 8 + idx] +
                  lsw[(hg + 4) * 8 + idx] + lsw[(hg + 6) * 8 + idx];
        g_pl[b][c][tid] = s;
        g_pm[b][c][tid] = 0.f;
    }
}

// ======================= scalar GEMM path (unchanged) =======================
__device__ __forceinline__ void gemm_tile(const float* __restrict__ X,
                                          const float* __restrict__ W,
                                          int wN, int col0,
                                          float* __restrict__ part, int pstride,
                                          int kc0) {
    __shared__ float Xs[64][17];
    __shared__ float Ws[16][64];
    const int tid = threadIdx.x;
    const int colg = tid & 7;
    const int rowg = tid >> 3;

    ull acc[4][4];
#pragma unroll
    for (int j = 0; j < 4; j++)
#pragma unroll
        for (int p = 0; p < 4; p++) acc[j][p] = 0ull;

    float4 xpre[2], wpre[2];
    const int xr = tid >> 2, xq = (tid & 3) * 4;
    const int wk = tid >> 4, wq = (tid & 15) * 4;
#pragma unroll
    for (int j = 0; j < 2; j++) {
        xpre[j] = *(const float4*)&X[(size_t)(xr + 32 * j) * EE + kc0 + xq];
        wpre[j] = *(const float4*)&W[(size_t)(kc0 + wk + 8 * j) * wN + col0 + wq];
    }
    for (int k0 = kc0; k0 < kc0 + KCH; k0 += 16) {
        __syncthreads();
#pragma unroll
        for (int j = 0; j < 2; j++) {
            float4 xv = xpre[j];
            Xs[xr + 32 * j][xq + 0] = xv.x;
            Xs[xr + 32 * j][xq + 1] = xv.y;
            Xs[xr + 32 * j][xq + 2] = xv.z;
            Xs[xr + 32 * j][xq + 3] = xv.w;
            *(float4*)&Ws[wk + 8 * j][wq] = wpre[j];
        }
        __syncthreads();
        if (k0 + 16 < kc0 + KCH) {
#pragma unroll
            for (int j = 0; j < 2; j++) {
                xpre[j] = *(const float4*)&X[(size_t)(xr + 32 * j) * EE + k0 + 16 + xq];
                wpre[j] = *(const float4*)&W[(size_t)(k0 + 16 + wk + 8 * j) * wN + col0 + wq];
            }
        }
#pragma unroll
        for (int kk = 0; kk < 16; kk++) {
            ulonglong2 wa = *(const ulonglong2*)&Ws[kk][colg * 8];
            ulonglong2 wb = *(const ulonglong2*)&Ws[kk][colg * 8 + 4];
#pragma unroll
            for (int j = 0; j < 4; j++) {
                float xv = Xs[rowg * 4 + j][kk];
                ull x2 = f2u(xv, xv);
                acc[j][0] = ffma2u(x2, wa.x, acc[j][0]);
                acc[j][1] = ffma2u(x2, wa.y, acc[j][1]);
                acc[j][2] = ffma2u(x2, wb.x, acc[j][2]);
                acc[j][3] = ffma2u(x2, wb.y, acc[j][3]);
            }
        }
    }
#pragma unroll
    for (int j = 0; j < 4; j++) {
        float* pr = part + (size_t)(rowg * 4 + j) * pstride + colg * 8;
#pragma unroll
        for (int p = 0; p < 4; p++) *(float2*)&pr[p * 2] = u2f(acc[j][p]);
    }
}

__global__ void __launch_bounds__(128) qkv_kernel(const float* __restrict__ x,
                                                  const float* __restrict__ Wq,
                                                  const float* __restrict__ Wk,
                                                  const float* __restrict__ Wv) {
    const int tile = blockIdx.x;
    const int ks = blockIdx.y;
    const int kc0 = ks * KCH;
    if (tile < 32) {
        gemm_tile(x, Wq, EE, tile * 64, &g_part[ks][0][tile * 64], 2304, kc0);
    } else if (tile < 34) {
        gemm_tile(x, Wk, DD, (tile - 32) * 64,
                  &g_part[ks][0][2048 + (tile - 32) * 64], 2304, kc0);
    } else {
        gemm_tile(x, Wv, DD, (tile - 34) * 64,
                  &g_part[ks][0][2176 + (tile - 34) * 64], 2304, kc0);
    }
}

__global__ void __launch_bounds__(192) qkv_reduce(const float* __restrict__ bq,
                                                  const float* __restrict__ bk,
                                                  const float* __restrict__ bv) {
    const int b = blockIdx.x;
    const int i = blockIdx.y * 192 + threadIdx.x;
    const int c = i * 4;
    float4 s = make_float4(0.f, 0.f, 0.f, 0.f);
#pragma unroll
    for (int ks = 0; ks < KSPLIT; ks++) {
        float4 p = *(const float4*)&g_part[ks][b][c];
        s.x += p.x; s.y += p.y; s.z += p.z; s.w += p.w;
    }
    if (c < 2048) {
        float4 bb = *(const float4*)&bq[c];
        s.x += bb.x; s.y += bb.y; s.z += bb.z; s.w += bb.w;
        *(float4*)&g_q[b][c] = s;
    } else if (c < 2176) {
        float4 bb = *(const float4*)&bk[c - 2048];
        s.x += bb.x; s.y += bb.y; s.z += bb.z; s.w += bb.w;
        *(float4*)&g_kn[b][c - 2048] = s;
    } else {
        float4 bb = *(const float4*)&bv[c - 2176];
        s.x += bb.x; s.y += bb.y; s.z += bb.z; s.w += bb.w;
        *(float4*)&g_vn[b][c - 2176] = s;
    }
}

__global__ void __launch_bounds__(256) combine_kernel() {
    const int b = blockIdx.x;
    const int i = blockIdx.y * 256 + threadIdx.x;
    const int h = i >> 5;
    const int dq = (i & 31) * 4;
    float M = -1e30f;
#pragma unroll
    for (int cc = 0; cc < NSPLIT; cc++) M = fmaxf(M, g_pm[b][cc][h]);
    float den = 0.f;
    float e[NSPLIT];
#pragma unroll
    for (int cc = 0; cc < NSPLIT; cc++) {
        e[cc] = __expf(g_pm[b][cc][h] - M);
        den += e[cc] * g_pl[b][cc][h];
    }
    float inv = 1.f / den;
    float4 acc = make_float4(0.f, 0.f, 0.f, 0.f);
#pragma unroll
    for (int cc = 0; cc < NSPLIT; cc++) {
        float wgt = e[cc] * inv;
        float4 p = *(const float4*)&g_po[b][cc][h][dq];
        acc.x += wgt * p.x; acc.y += wgt * p.y;
        acc.z += wgt * p.z; acc.w += wgt * p.w;
    }
    *(float4*)&g_attn[b][h * DD + dq] = acc;
}

__global__ void __launch_bounds__(128) oproj_kernel(const float* __restrict__ Wo) {
    const int tile = blockIdx.x;
    const int ks = blockIdx.y;
    gemm_tile(&g_attn[0][0], Wo, EE, tile * 64, &g_part2[ks][0][tile * 64], EE,
              ks * KCH);
}

__global__ void __launch_bounds__(256) oproj_reduce(const float* __restrict__ bo,
                                                    float* __restrict__ out) {
    const int b = blockIdx.x;
    const int i = blockIdx.y * 256 + threadIdx.x;
    const int cq = i * 4;
    float4 s = make_float4(0.f, 0.f, 0.f, 0.f);
#pragma unroll
    for (int ks = 0; ks < KSPLIT; ks++) {
        float4 p = *(const float4*)&g_part2[ks][b][cq];
        s.x += p.x; s.y += p.y; s.z += p.z; s.w += p.w;
    }
    float4 bb = *(const float4*)&bo[cq];
    s.x += bb.x; s.y += bb.y; s.z += bb.z; s.w += bb.w;
    *(float4*)&out[(size_t)b * EE + cq] = s;
}

extern "C" void kernel_launch(void* const* d_in, const int* in_sizes, int n_in,
                              void* d_out, int out_size) {
    const float* x  = (const float*)d_in[0];
    const float* kc = (const float*)d_in[1];
    const float* vc = (const float*)d_in[2];
    const int* pos  = (const int*)d_in[3];
    const float* Wq = (const float*)d_in[4];
    const float* bq = (const float*)d_in[5];
    const float* Wk = (const float*)d_in[6];
    const float* bk = (const float*)d_in[7];
    const float* Wv = (const float*)d_in[8];
    const float* bv = (const float*)d_in[9];
    const float* Wo = (const float*)d_in[10];
    const float* bo = (const float*)d_in[11];
    float* out = (float*)d_out;

    cudaFuncSetAttribute(attn_kernel, cudaFuncAttributeMaxDynamicSharedMemorySize,
                         SMEM_ATTN);

    qkv_kernel<<<dim3(36, KSPLIT), 128>>>(x, Wq, Wk, Wv);            // 1
    qkv_reduce<<<dim3(BB, 3), 192>>>(bq, bk, bv);                    // 2
    noop_kernel<<<1, 32>>>();                                        // 3
    attn_kernel<<<dim3(NSPLIT, BB), 256, SMEM_ATTN>>>(kc, vc, pos);  // 4 (ncu)
    combine_kernel<<<dim3(BB, 2), 256>>>();                          // 5
    oproj_kernel<<<dim3(32, KSPLIT), 128>>>(Wo);                     // 6
    oproj_reduce<<<dim3(BB, 2), 256>>>(bo, out);                     // 7
}

// round 14
// speedup vs baseline: 1.0977x; 1.0977x over previous
#include <cuda_runtime.h>
#include <cstdint>

#define BB 64
#define HH 16
#define DD 128
#define S_TOT 4096
#define EE 2048
#define NSPLIT 4
#define CHUNK 1024
#define SUB 64
#define KSPLIT 8
#define KCH 256

typedef unsigned long long ull;

__device__ float g_q[BB][EE];
__device__ float g_kn[BB][DD];
__device__ float g_vn[BB][DD];
__device__ float g_po[BB][NSPLIT][HH][DD];
__device__ float g_pm[BB][NSPLIT][HH];
__device__ float g_pl[BB][NSPLIT][HH];
__device__ float g_attn[BB][EE];
__device__ float g_part[KSPLIT][BB][2304];
__device__ float g_part2[KSPLIT][BB][EE];

__device__ __forceinline__ ull ffma2u(ull a, ull b, ull c) {
    ull d;
    asm("fma.rn.f32x2 %0, %1, %2, %3;" : "=l"(d) : "l"(a), "l"(b), "l"(c));
    return d;
}
__device__ __forceinline__ ull f2u(float x, float y) {
    ull u;
    asm("mov.b64 %0, {%1,%2};" : "=l"(u) : "f"(x), "f"(y));
    return u;
}
__device__ __forceinline__ float2 u2f(ull u) {
    float2 f;
    asm("mov.b64 {%0,%1}, %2;" : "=f"(f.x), "=f"(f.y) : "l"(u));
    return f;
}

__global__ void noop_kernel() {}

// ============ attention: mma.sync 3xTF32, double-buffered cp.async ============
// smem: kb[64][132] @0 | vb[64][132] @33792 | qh @67584 | ql @76032
//       PH[64][24] @84480 | PL @90624 | lsw @96768 ; total 97024
#define KB_OFF 0
#define VB_OFF 33792
#define QH_OFF 67584
#define QL_OFF 76032
#define PH_OFF 84480
#define PL_OFF 90624
#define LS_OFF 96768
#define SMEM_ATTN 97024

__device__ __forceinline__ uint32_t cvt_tf32(float x) {
    uint32_t r;
    asm("cvt.rna.tf32.f32 %0, %1;" : "=r"(r) : "f"(x));
    return r;
}
__device__ __forceinline__ void mma8(float* d, const uint32_t* a,
                                     const uint32_t* b) {
    asm volatile(
        "mma.sync.aligned.m16n8k8.row.col.f32.tf32.tf32.f32 "
        "{%0,%1,%2,%3},{%4,%5,%6,%7},{%8,%9},{%0,%1,%2,%3};"
        : "+f"(d[0]), "+f"(d[1]), "+f"(d[2]), "+f"(d[3])
        : "r"(a[0]), "r"(a[1]), "r"(a[2]), "r"(a[3]), "r"(b[0]), "r"(b[1]));
}
__device__ __forceinline__ void split_tf32(float x, uint32_t& hi, uint32_t& lo) {
    hi = cvt_tf32(x);
    lo = cvt_tf32(x - __uint_as_float(hi));
}
__device__ __forceinline__ void cp16(uint32_t dst, const void* src) {
    asm volatile("cp.async.cg.shared.global [%0], [%1], 16;"
                 :: "r"(dst), "l"(src));
}
__device__ __forceinline__ void cp_commit() {
    asm volatile("cp.async.commit_group;");
}
__device__ __forceinline__ void cp_wait1() {
    asm volatile("cp.async.wait_group 1;" ::: "memory");
}

__global__ void __launch_bounds__(256, 2) attn_kernel(
    const float* __restrict__ kc, const float* __restrict__ vc,
    const int* __restrict__ pos) {
    extern __shared__ char smem[];
    float* kb = (float*)(smem + KB_OFF);
    float* vb = (float*)(smem + VB_OFF);
    uint32_t* qh = (uint32_t*)(smem + QH_OFF);
    uint32_t* ql = (uint32_t*)(smem + QL_OFF);
    uint32_t* PH = (uint32_t*)(smem + PH_OFF);
    uint32_t* PL = (uint32_t*)(smem + PL_OFF);
    float* lsw = (float*)(smem + LS_OFF);
    const uint32_t kbs = (uint32_t)__cvta_generic_to_shared(kb);
    const uint32_t vbs = (uint32_t)__cvta_generic_to_shared(vb);

    const int c = blockIdx.x, b = blockIdx.y;
    const int tid = threadIdx.x, w = tid >> 5, l = tid & 31;
    const int g = l >> 2, t = l & 3;

    const int p_glob = pos[b];
    const size_t base = (size_t)b * S_TOT * DD;
    const float scale = 0.08838834764831845f;  // 1/sqrt(128)

    // per-thread load slots
    const int lds = tid >> 5;   // s = lds + 8*it
    const int ldq = tid & 31;

    // ---- prologue: issue K0 then V0 (separate groups) ----
    {
        const int sbase = c * CHUNK;
#pragma unroll
        for (int it = 0; it < 8; it++) {
            int s = lds + 8 * it;
            int gs = sbase + s;
            const float* src = (gs == p_glob)
                                   ? &g_kn[b][ldq * 4]
                                   : &kc[base + (size_t)gs * DD + ldq * 4];
            cp16(kbs + (uint32_t)(s * 132 + ldq * 4) * 4, src);
        }
        cp_commit();
#pragma unroll
        for (int it = 0; it < 8; it++) {
            int s = lds + 8 * it;
            int gs = sbase + s;
            const float* src = (gs == p_glob)
                                   ? &g_vn[b][ldq * 4]
                                   : &vc[base + (size_t)gs * DD + ldq * 4];
            cp16(vbs + (uint32_t)(s * 132 + ldq * 4) * 4, src);
        }
        cp_commit();
    }

    // stage q pre-split into hi/lo tf32 planes (overlaps with K0/V0 flight)
    for (int i = tid; i < 2048; i += 256) {
        int h = i >> 7, d = i & 127;
        uint32_t hi, lo;
        split_tf32(g_q[b][h * 128 + d], hi, lo);
        qh[h * 132 + d] = hi;
        ql[h * 132 + d] = lo;
    }

    // QK geometry: warp -> 16 slots, 8 heads
    const int s0 = (w >> 1) * 16;
    const int h0 = (w & 1) * 8;
    // PV geometry: warp -> 16 dims, all heads
    const int d0 = w * 16;

    float accp[2][4];
#pragma unroll
    for (int n = 0; n < 2; n++)
#pragma unroll
        for (int j = 0; j < 4; j++) accp[n][j] = 0.f;
    float lsacc[2] = {0.f, 0.f};

    for (int sub = 0; sub < CHUNK / SUB; sub++) {
        // ---- K_n ready (pending: {K_n, V_n} -> wait leaves V_n in flight) ----
        cp_wait1();
        __syncthreads();

        // ---- QK: C[16 slots x 8 heads], 3xTF32 ----
        float accq[4] = {0.f, 0.f, 0.f, 0.f};
#pragma unroll
        for (int k = 0; k < 16; k++) {
            const int kb_ = k * 8;
            float a0 = kb[(s0 + g) * 132 + kb_ + t];
            float a1 = kb[(s0 + g + 8) * 132 + kb_ + t];
            float a2 = kb[(s0 + g) * 132 + kb_ + t + 4];
            float a3 = kb[(s0 + g + 8) * 132 + kb_ + t + 4];
            uint32_t ah[4], al[4];
            split_tf32(a0, ah[0], al[0]);
            split_tf32(a1, ah[1], al[1]);
            split_tf32(a2, ah[2], al[2]);
            split_tf32(a3, ah[3], al[3]);
            uint32_t bh[2], bl[2];
            bh[0] = qh[(h0 + g) * 132 + kb_ + t];
            bh[1] = qh[(h0 + g) * 132 + kb_ + t + 4];
            bl[0] = ql[(h0 + g) * 132 + kb_ + t];
            bl[1] = ql[(h0 + g) * 132 + kb_ + t + 4];
            mma8(accq, ah, bh);
            mma8(accq, ah, bl);
            mma8(accq, al, bh);
        }

        // ---- epilogue: deferred softmax, P hi/lo ----
#pragma unroll
        for (int j = 0; j < 4; j++) {
            float p = __expf(fminf(accq[j] * scale, 70.f));
            int slot = s0 + g + ((j >= 2) ? 8 : 0);
            int h = h0 + 2 * t + (j & 1);
            lsacc[j & 1] += p;
            uint32_t phi, plo;
            split_tf32(p, phi, plo);
            PH[slot * 24 + h] = phi;
            PL[slot * 24 + h] = plo;
        }
        __syncthreads();  // P visible; kb fully consumed

        // ---- issue K_{n+1} into kb (overlaps PV below) ----
        if (sub + 1 < CHUNK / SUB) {
            const int nbase = c * CHUNK + (sub + 1) * SUB;
#pragma unroll
            for (int it = 0; it < 8; it++) {
                int s = lds + 8 * it;
                int gs = nbase + s;
                const float* src = (gs == p_glob)
                                       ? &g_kn[b][ldq * 4]
                                       : &kc[base + (size_t)gs * DD + ldq * 4];
                cp16(kbs + (uint32_t)(s * 132 + ldq * 4) * 4, src);
            }
        }
        cp_commit();  // pending: {V_n, K_{n+1}}

        // ---- V_n ready ----
        cp_wait1();
        __syncthreads();

        // ---- PV: C[16 dims x 16 heads] += V^T . P, 8 k-steps ----
#pragma unroll
        for (int k = 0; k < 8; k++) {
            const int kb_ = k * 8;
            float a0 = vb[(kb_ + t) * 132 + d0 + g];
            float a1 = vb[(kb_ + t) * 132 + d0 + g + 8];
            float a2 = vb[(kb_ + t + 4) * 132 + d0 + g];
            float a3 = vb[(kb_ + t + 4) * 132 + d0 + g + 8];
            uint32_t ah[4], al[4];
            split_tf32(a0, ah[0], al[0]);
            split_tf32(a1, ah[1], al[1]);
            split_tf32(a2, ah[2], al[2]);
            split_tf32(a3, ah[3], al[3]);
#pragma unroll
            for (int n = 0; n < 2; n++) {
                uint32_t bh[2], bl[2];
                bh[0] = PH[(kb_ + t) * 24 + n * 8 + g];
                bh[1] = PH[(kb_ + t + 4) * 24 + n * 8 + g];
                bl[0] = PL[(kb_ + t) * 24 + n * 8 + g];
                bl[1] = PL[(kb_ + t + 4) * 24 + n * 8 + g];
                mma8(accp[n], ah, bh);
                mma8(accp[n], ah, bl);
                mma8(accp[n], al, bh);
            }
        }
        __syncthreads();  // vb consumed

        // ---- issue V_{n+1} into vb ----
        if (sub + 1 < CHUNK / SUB) {
            const int nbase = c * CHUNK + (sub + 1) * SUB;
#pragma unroll
            for (int it = 0; it < 8; it++) {
                int s = lds + 8 * it;
                int gs = nbase + s;
                const float* src = (gs == p_glob)
                                       ? &g_vn[b][ldq * 4]
                                       : &vc[base + (size_t)gs * DD + ldq * 4];
                cp16(vbs + (uint32_t)(s * 132 + ldq * 4) * 4, src);
            }
        }
        cp_commit();  // pending: {K_{n+1}, V_{n+1}}
    }

    // ---- write PV outputs ----
#pragma unroll
    for (int n = 0; n < 2; n++) {
#pragma unroll
        for (int j = 0; j < 4; j++) {
            int d = d0 + g + ((j >= 2) ? 8 : 0);
            int h = n * 8 + 2 * t + (j & 1);
            g_po[b][c][h][d] = accp[n][j];
        }
    }
    // ---- denominators ----
#pragma unroll
    for (int jj = 0; jj < 2; jj++) {
        float v = lsacc[jj];
        v += __shfl_xor_sync(0xffffffffu, v, 4);
        v += __shfl_xor_sync(0xffffffffu, v, 8);
        v += __shfl_xor_sync(0xffffffffu, v, 16);
        if (g == 0) lsw[w * 8 + 2 * t + jj] = v;
    }
    __syncthreads();
    if (tid < 16) {
        int hg = tid >> 3, idx = tid & 7;
        float s = lsw[hg * 8 + idx] + lsw[(hg + 2) * 8 + idx] +
                  lsw[(hg + 4) * 8 + idx] + lsw[(hg + 6) * 8 + idx];
        g_pl[b][c][tid] = s;
        g_pm[b][c][tid] = 0.f;
    }
}

// ======================= scalar GEMM path (unchanged) =======================
__device__ __forceinline__ void gemm_tile(const float* __restrict__ X,
                                          const float* __restrict__ W,
                                          int wN, int col0,
                                          float* __restrict__ part, int pstride,
                                          int kc0) {
    __shared__ float Xs[64][17];
    __shared__ float Ws[16][64];
    const int tid = threadIdx.x;
    const int colg = tid & 7;
    const int rowg = tid >> 3;

    ull acc[4][4];
#pragma unroll
    for (int j = 0; j < 4; j++)
#pragma unroll
        for (int p = 0; p < 4; p++) acc[j][p] = 0ull;

    float4 xpre[2], wpre[2];
    const int xr = tid >> 2, xq = (tid & 3) * 4;
    const int wk = tid >> 4, wq = (tid & 15) * 4;
#pragma unroll
    for (int j = 0; j < 2; j++) {
        xpre[j] = *(const float4*)&X[(size_t)(xr + 32 * j) * EE + kc0 + xq];
        wpre[j] = *(const float4*)&W[(size_t)(kc0 + wk + 8 * j) * wN + col0 + wq];
    }
    for (int k0 = kc0; k0 < kc0 + KCH; k0 += 16) {
        __syncthreads();
#pragma unroll
        for (int j = 0; j < 2; j++) {
            float4 xv = xpre[j];
            Xs[xr + 32 * j][xq + 0] = xv.x;
            Xs[xr + 32 * j][xq + 1] = xv.y;
            Xs[xr + 32 * j][xq + 2] = xv.z;
            Xs[xr + 32 * j][xq + 3] = xv.w;
            *(float4*)&Ws[wk + 8 * j][wq] = wpre[j];
        }
        __syncthreads();
        if (k0 + 16 < kc0 + KCH) {
#pragma unroll
            for (int j = 0; j < 2; j++) {
                xpre[j] = *(const float4*)&X[(size_t)(xr + 32 * j) * EE + k0 + 16 + xq];
                wpre[j] = *(const float4*)&W[(size_t)(k0 + 16 + wk + 8 * j) * wN + col0 + wq];
            }
        }
#pragma unroll
        for (int kk = 0; kk < 16; kk++) {
            ulonglong2 wa = *(const ulonglong2*)&Ws[kk][colg * 8];
            ulonglong2 wb = *(const ulonglong2*)&Ws[kk][colg * 8 + 4];
#pragma unroll
            for (int j = 0; j < 4; j++) {
                float xv = Xs[rowg * 4 + j][kk];
                ull x2 = f2u(xv, xv);
                acc[j][0] = ffma2u(x2, wa.x, acc[j][0]);
                acc[j][1] = ffma2u(x2, wa.y, acc[j][1]);
                acc[j][2] = ffma2u(x2, wb.x, acc[j][2]);
                acc[j][3] = ffma2u(x2, wb.y, acc[j][3]);
            }
        }
    }
#pragma unroll
    for (int j = 0; j < 4; j++) {
        float* pr = part + (size_t)(rowg * 4 + j) * pstride + colg * 8;
#pragma unroll
        for (int p = 0; p < 4; p++) *(float2*)&pr[p * 2] = u2f(acc[j][p]);
    }
}

__global__ void __launch_bounds__(128) qkv_kernel(const float* __restrict__ x,
                                                  const float* __restrict__ Wq,
                                                  const float* __restrict__ Wk,
                                                  const float* __restrict__ Wv) {
    const int tile = blockIdx.x;
    const int ks = blockIdx.y;
    const int kc0 = ks * KCH;
    if (tile < 32) {
        gemm_tile(x, Wq, EE, tile * 64, &g_part[ks][0][tile * 64], 2304, kc0);
    } else if (tile < 34) {
        gemm_tile(x, Wk, DD, (tile - 32) * 64,
                  &g_part[ks][0][2048 + (tile - 32) * 64], 2304, kc0);
    } else {
        gemm_tile(x, Wv, DD, (tile - 34) * 64,
                  &g_part[ks][0][2176 + (tile - 34) * 64], 2304, kc0);
    }
}

__global__ void __launch_bounds__(192) qkv_reduce(const float* __restrict__ bq,
                                                  const float* __restrict__ bk,
                                                  const float* __restrict__ bv) {
    const int b = blockIdx.x;
    const int i = blockIdx.y * 192 + threadIdx.x;
    const int c = i * 4;
    float4 s = make_float4(0.f, 0.f, 0.f, 0.f);
#pragma unroll
    for (int ks = 0; ks < KSPLIT; ks++) {
        float4 p = *(const float4*)&g_part[ks][b][c];
        s.x += p.x; s.y += p.y; s.z += p.z; s.w += p.w;
    }
    if (c < 2048) {
        float4 bb = *(const float4*)&bq[c];
        s.x += bb.x; s.y += bb.y; s.z += bb.z; s.w += bb.w;
        *(float4*)&g_q[b][c] = s;
    } else if (c < 2176) {
        float4 bb = *(const float4*)&bk[c - 2048];
        s.x += bb.x; s.y += bb.y; s.z += bb.z; s.w += bb.w;
        *(float4*)&g_kn[b][c - 2048] = s;
    } else {
        float4 bb = *(const float4*)&bv[c - 2176];
        s.x += bb.x; s.y += bb.y; s.z += bb.z; s.w += bb.w;
        *(float4*)&g_vn[b][c - 2176] = s;
    }
}

__global__ void __launch_bounds__(256) combine_kernel() {
    const int b = blockIdx.x;
    const int i = blockIdx.y * 256 + threadIdx.x;
    const int h = i >> 5;
    const int dq = (i & 31) * 4;
    float M = -1e30f;
#pragma unroll
    for (int cc = 0; cc < NSPLIT; cc++) M = fmaxf(M, g_pm[b][cc][h]);
    float den = 0.f;
    float e[NSPLIT];
#pragma unroll
    for (int cc = 0; cc < NSPLIT; cc++) {
        e[cc] = __expf(g_pm[b][cc][h] - M);
        den += e[cc] * g_pl[b][cc][h];
    }
    float inv = 1.f / den;
    float4 acc = make_float4(0.f, 0.f, 0.f, 0.f);
#pragma unroll
    for (int cc = 0; cc < NSPLIT; cc++) {
        float wgt = e[cc] * inv;
        float4 p = *(const float4*)&g_po[b][cc][h][dq];
        acc.x += wgt * p.x; acc.y += wgt * p.y;
        acc.z += wgt * p.z; acc.w += wgt * p.w;
    }
    *(float4*)&g_attn[b][h * DD + dq] = acc;
}

__global__ void __launch_bounds__(128) oproj_kernel(const float* __restrict__ Wo) {
    const int tile = blockIdx.x;
    const int ks = blockIdx.y;
    gemm_tile(&g_attn[0][0], Wo, EE, tile * 64, &g_part2[ks][0][tile * 64], EE,
              ks * KCH);
}

__global__ void __launch_bounds__(256) oproj_reduce(const float* __restrict__ bo,
                                                    float* __restrict__ out) {
    const int b = blockIdx.x;
    const int i = blockIdx.y * 256 + threadIdx.x;
    const int cq = i * 4;
    float4 s = make_float4(0.f, 0.f, 0.f, 0.f);
#pragma unroll
    for (int ks = 0; ks < KSPLIT; ks++) {
        float4 p = *(const float4*)&g_part2[ks][b][cq];
        s.x += p.x; s.y += p.y; s.z += p.z; s.w += p.w;
    }
    float4 bb = *(const float4*)&bo[cq];
    s.x += bb.x; s.y += bb.y; s.z += bb.z; s.w += bb.w;
    *(float4*)&out[(size_t)b * EE + cq] = s;
}

extern "C" void kernel_launch(void* const* d_in, const int* in_sizes, int n_in,
                              void* d_out, int out_size) {
    const float* x  = (const float*)d_in[0];
    const float* kc = (const float*)d_in[1];
    const float* vc = (const float*)d_in[2];
    const int* pos  = (const int*)d_in[3];
    const float* Wq = (const float*)d_in[4];
    const float* bq = (const float*)d_in[5];
    const float* Wk = (const float*)d_in[6];
    const float* bk = (const float*)d_in[7];
    const float* Wv = (const float*)d_in[8];
    const float* bv = (const float*)d_in[9];
    const float* Wo = (const float*)d_in[10];
    const float* bo = (const float*)d_in[11];
    float* out = (float*)d_out;

    cudaFuncSetAttribute(attn_kernel, cudaFuncAttributeMaxDynamicSharedMemorySize,
                         SMEM_ATTN);

    qkv_kernel<<<dim3(36, KSPLIT), 128>>>(x, Wq, Wk, Wv);            // 1
    qkv_reduce<<<dim3(BB, 3), 192>>>(bq, bk, bv);                    // 2
    noop_kernel<<<1, 32>>>();                                        // 3
    attn_kernel<<<dim3(NSPLIT, BB), 256, SMEM_ATTN>>>(kc, vc, pos);  // 4 (ncu)
    combine_kernel<<<dim3(BB, 2), 256>>>();                          // 5
    oproj_kernel<<<dim3(32, KSPLIT), 128>>>(Wo);                     // 6
    oproj_reduce<<<dim3(BB, 2), 256>>>(bo, out);                     // 7
}